// round 16
// baseline (speedup 1.0000x reference)
#include <cuda_runtime.h>

// context[b,d] = sum_t keys[b,t,d]   (softmax over size-1 axis == 1; rest dead)
// R16 = R13 champion (dedup'd prefetch streamer, confirmed 38.9/38.4us) with
// PF deepened 8 -> 12. R8's PF=16 regression was measured with ALL-LANE
// prefetch (32 req/warp/iter); dedup cut that 8x, so window depth is untested
// in the clean regime. Everything else byte-identical to R13.

#define B_SZ 32
#define T_LEN 4096
#define D_DIM 512           // floats
#define D4 (D_DIM / 4)      // 128 float4 per row
#define PF 12               // prefetch distance (rows)

__global__ __launch_bounds__(1024, 2)
void keys_sum_kernel(const float4* __restrict__ keys4, float4* __restrict__ out4) {
    const int tid   = threadIdx.x;
    const int col   = tid & 15;          // 0..15 within chunk
    const int part  = tid >> 4;          // 0..63 T-partition
    const int chunk = blockIdx.x;        // 0..7
    const int b     = blockIdx.y;        // 0..31

    const int col4 = chunk * 16 + col;   // global float4 column 0..127
    const float4* p = keys4 + (b * T_LEN + part * 64) * D4 + col4;

    // one prefetching lane per 128B line (8 lanes x 16B = 1 line)
    const bool pf_lane = ((tid & 7) == 0);

    float4 acc = make_float4(0.f, 0.f, 0.f, 0.f);

    #pragma unroll 8
    for (int i = 0; i < 64 - PF; ++i) {
        if (pf_lane)
            asm volatile("prefetch.global.L2 [%0];" :: "l"(p + (i + PF) * D4));
        float4 v = __ldcs(p + i * D4);
        acc.x += v.x; acc.y += v.y; acc.z += v.z; acc.w += v.w;
    }
    #pragma unroll
    for (int i = 64 - PF; i < 64; ++i) {
        float4 v = __ldcs(p + i * D4);
        acc.x += v.x; acc.y += v.y; acc.z += v.z; acc.w += v.w;
    }

    __shared__ float4 sm[1024];
    sm[tid] = acc;
    __syncthreads();

    // reduce across the 64 T-partitions (stride-16 layout keeps per-col sums)
    #pragma unroll
    for (int s = 512; s >= 16; s >>= 1) {
        if (tid < s) {
            float4 o = sm[tid + s];
            float4 m = sm[tid];
            m.x += o.x; m.y += o.y; m.z += o.z; m.w += o.w;
            sm[tid] = m;
        }
        __syncthreads();
    }

    if (tid < 16) {
        out4[b * D4 + chunk * 16 + tid] = sm[tid];
    }
}

extern "C" void kernel_launch(void* const* d_in, const int* in_sizes, int n_in,
                              void* d_out, int out_size) {
    // metadata order: query[0], keys[1], Ws[2], Wh[3], W[4]; only keys is live.
    const float* keys = (const float*)d_in[1];
    float* out = (float*)d_out;

    dim3 grid(D4 / 16, B_SZ);   // (8, 32) = 256 blocks, one resident wave
    keys_sum_kernel<<<grid, 1024>>>((const float4*)keys, (float4*)out);
}

// round 17
// speedup vs baseline: 1.0566x; 1.0566x over previous
#include <cuda_runtime.h>

// context[b,d] = sum_t keys[b,t,d]   (softmax over size-1 axis == 1; rest dead)
// FINAL (= R13, confirmed 38.9/38.4us; PF sweep closed: 8 > 12 > 16).
// 256x1024 direct-output streamer: __ldcs 128-bit demand loads + dedup'd
// L2 prefetch (one lane per 128B line) at PF=8 rows, unroll 8.
// ~6.6 TB/s effective — at the sm_103a path-independent streaming ceiling.
// Regressions on file: 2-kernel finalize, fused finalize (fences), grid
// rebalance, PF=12/16, L2 evict_last residency, LDG.256, unroll 16.

#define B_SZ 32
#define T_LEN 4096
#define D_DIM 512           // floats
#define D4 (D_DIM / 4)      // 128 float4 per row
#define PF 8                // prefetch distance (rows) — swept optimum

__global__ __launch_bounds__(1024, 2)
void keys_sum_kernel(const float4* __restrict__ keys4, float4* __restrict__ out4) {
    const int tid   = threadIdx.x;
    const int col   = tid & 15;          // 0..15 within chunk
    const int part  = tid >> 4;          // 0..63 T-partition
    const int chunk = blockIdx.x;        // 0..7
    const int b     = blockIdx.y;        // 0..31

    const int col4 = chunk * 16 + col;   // global float4 column 0..127
    const float4* p = keys4 + (b * T_LEN + part * 64) * D4 + col4;

    // one prefetching lane per 128B line (8 lanes x 16B = 1 line)
    const bool pf_lane = ((tid & 7) == 0);

    float4 acc = make_float4(0.f, 0.f, 0.f, 0.f);

    #pragma unroll 8
    for (int i = 0; i < 64 - PF; ++i) {
        if (pf_lane)
            asm volatile("prefetch.global.L2 [%0];" :: "l"(p + (i + PF) * D4));
        float4 v = __ldcs(p + i * D4);
        acc.x += v.x; acc.y += v.y; acc.z += v.z; acc.w += v.w;
    }
    #pragma unroll
    for (int i = 64 - PF; i < 64; ++i) {
        float4 v = __ldcs(p + i * D4);
        acc.x += v.x; acc.y += v.y; acc.z += v.z; acc.w += v.w;
    }

    __shared__ float4 sm[1024];
    sm[tid] = acc;
    __syncthreads();

    // reduce across the 64 T-partitions (stride-16 layout keeps per-col sums)
    #pragma unroll
    for (int s = 512; s >= 16; s >>= 1) {
        if (tid < s) {
            float4 o = sm[tid + s];
            float4 m = sm[tid];
            m.x += o.x; m.y += o.y; m.z += o.z; m.w += o.w;
            sm[tid] = m;
        }
        __syncthreads();
    }

    if (tid < 16) {
        out4[b * D4 + chunk * 16 + tid] = sm[tid];
    }
}

extern "C" void kernel_launch(void* const* d_in, const int* in_sizes, int n_in,
                              void* d_out, int out_size) {
    // metadata order: query[0], keys[1], Ws[2], Wh[3], W[4]; only keys is live.
    const float* keys = (const float*)d_in[1];
    float* out = (float*)d_out;

    dim3 grid(D4 / 16, B_SZ);   // (8, 32) = 256 blocks, one resident wave
    keys_sum_kernel<<<grid, 1024>>>((const float4*)keys, (float4*)out);
}